// round 13
// baseline (speedup 1.0000x reference)
#include <cuda_runtime.h>
#include <cuda_fp16.h>
#include <cstdint>

#define NN     100000
#define HH     128
#define TT     32
#define MDIM   16
#define ES     600000
#define ED     600000
#define NSTR   64        // halves per node in interleaved tables (128B)

// ---------------- scratch ----------------
// Interleaved per-node tables (128B each): [proj 32h | mask16 16h | pad 16h]
__device__ __align__(16) __half g_A[NN * NSTR];  // Ps + mask16  (src-side gather)
__device__ __align__(16) __half g_B[NN * NSTR];  // Pd(+bias) + mask16 (dst-side gather)
__device__ float g_ew_s[ES];
__device__ float g_ew_d[ED];
// propagation state: fp32 accumulator (atomics) + compact fp16 mirrors
__device__ __align__(16) float  g_n32pos[NN * MDIM];
__device__ __align__(16) float  g_n32dom[NN * MDIM];
__device__ __align__(16) __half g_c16pos[NN * MDIM];
__device__ __align__(16) __half g_c16dom[NN * MDIM];

// ---------------- helpers ----------------
__device__ __forceinline__ float fast_tanh(float s) {
    float r; asm("tanh.approx.f32 %0, %1;" : "=f"(r) : "f"(s)); return r;
}
__device__ __forceinline__ unsigned su32(const void* p) {
    return (unsigned)__cvta_generic_to_shared(p);
}

// ---------------- kernel 1: HMMA node projections + fused init -------------
#define XS_STRIDE 136
#define WP_STRIDE 72

__global__ void __launch_bounds__(128) proj_kernel(const float* __restrict__ x,
                                                   const float* __restrict__ Wt,
                                                   const float* __restrict__ bt,
                                                   const float* __restrict__ mask) {
    __shared__ __align__(16) __half Wp[128 * WP_STRIDE];
    __shared__ __align__(16) __half xs[64 * XS_STRIDE];
    int tid = threadIdx.x;
    int n0 = blockIdx.x * 64;

    // ---- fused init: mask -> n32 buffers + mask16 slots of g_A/g_B ----
    {
        const int n4 = NN * MDIM / 4;   // float4 count over mask
        for (int i = blockIdx.x * 128 + tid; i < n4; i += gridDim.x * 128) {
            float4 v = reinterpret_cast<const float4*>(mask)[i];
            reinterpret_cast<float4*>(g_n32pos)[i] = v;
            reinterpret_cast<float4*>(g_n32dom)[i] = v;
            __half2 h0 = __floats2half2_rn(v.x, v.y);
            __half2 h1 = __floats2half2_rn(v.z, v.w);
            uint2 packed = make_uint2(*reinterpret_cast<unsigned*>(&h0),
                                      *reinterpret_cast<unsigned*>(&h1));
            int n = i >> 2, q = i & 3;  // node, channel-quad
            *reinterpret_cast<uint2*>(&g_A[(size_t)n * NSTR + TT + q * 4]) = packed;
            *reinterpret_cast<uint2*>(&g_B[(size_t)n * NSTR + TT + q * 4]) = packed;
        }
    }

    for (int i = tid; i < 128 * 64; i += 128) {
        int h = i >> 6, j = i & 63;
        float w = (j < 32) ? Wt[h * 32 + j] : Wt[(128 + h) * 32 + (j - 32)];
        Wp[h * WP_STRIDE + j] = __float2half_rn(w);
    }
    for (int i = tid; i < 64 * 32; i += 128) {
        int r = i >> 5, c4 = i & 31;
        int node = n0 + r;
        float4 v = (node < NN)
                 ? reinterpret_cast<const float4*>(x)[(size_t)node * 32 + c4]
                 : make_float4(0.f, 0.f, 0.f, 0.f);
        *reinterpret_cast<__half2*>(&xs[r * XS_STRIDE + c4 * 4])     = __floats2half2_rn(v.x, v.y);
        *reinterpret_cast<__half2*>(&xs[r * XS_STRIDE + c4 * 4 + 2]) = __floats2half2_rn(v.z, v.w);
    }
    __syncthreads();

    int warp = tid >> 5, lane = tid & 31;
    int wb = warp * 16;

    float acc[8][4];
#pragma unroll
    for (int nt = 0; nt < 8; nt++)
#pragma unroll
        for (int j = 0; j < 4; j++) acc[nt][j] = 0.f;

    int a_row = wb + (lane & 15);
    int a_coff = (lane >> 4) * 8;
    int b_row = (lane & 15);

#pragma unroll
    for (int k = 0; k < 8; k++) {
        unsigned a0, a1, a2, a3;
        unsigned addrA = su32(&xs[a_row * XS_STRIDE + k * 16 + a_coff]);
        asm volatile("ldmatrix.sync.aligned.m8n8.x4.shared.b16 {%0,%1,%2,%3}, [%4];"
                     : "=r"(a0), "=r"(a1), "=r"(a2), "=r"(a3) : "r"(addrA));
#pragma unroll
        for (int nt = 0; nt < 8; nt++) {
            unsigned b0, b1;
            unsigned addrB = su32(&Wp[(k * 16 + b_row) * WP_STRIDE + nt * 8]);
            asm volatile("ldmatrix.sync.aligned.m8n8.x2.trans.shared.b16 {%0,%1}, [%2];"
                         : "=r"(b0), "=r"(b1) : "r"(addrB));
            asm volatile("mma.sync.aligned.m16n8k16.row.col.f32.f16.f16.f32 "
                         "{%0,%1,%2,%3}, {%4,%5,%6,%7}, {%8,%9}, {%0,%1,%2,%3};"
                         : "+f"(acc[nt][0]), "+f"(acc[nt][1]), "+f"(acc[nt][2]), "+f"(acc[nt][3])
                         : "r"(a0), "r"(a1), "r"(a2), "r"(a3), "r"(b0), "r"(b1));
        }
    }

    int row_l = wb + (lane >> 2);
    int col0 = (lane & 3) * 2;
#pragma unroll
    for (int nt = 0; nt < 8; nt++) {
        bool isPs = (nt < 4);
        __half* base = isPs ? g_A : g_B;
        int cc = isPs ? (nt * 8 + col0) : (nt * 8 + col0 - 32);
        float b0 = isPs ? 0.f : bt[cc];
        float b1 = isPs ? 0.f : bt[cc + 1];
        int nodeA = n0 + row_l;
        int nodeB = nodeA + 8;
        if (nodeA < NN)
            *reinterpret_cast<__half2*>(&base[(size_t)nodeA * NSTR + cc]) =
                __floats2half2_rn(acc[nt][0] + b0, acc[nt][1] + b1);
        if (nodeB < NN)
            *reinterpret_cast<__half2*>(&base[(size_t)nodeB * NSTR + cc]) =
                __floats2half2_rn(acc[nt][2] + b0, acc[nt][3] + b1);
    }
}

// ---------------- kernel 2: FUSED gate + propagation round 1 ---------------
// 2 lanes/edge. ALL src-side data (Ps + mask16) comes from ONE 128B line in
// g_A[src]; all dst-side data (Pd + mask16) from ONE line in g_B[dst].
__global__ void ewprop_kernel(const int* __restrict__ si, const int* __restrict__ di,
                              const float* __restrict__ sattr, const float* __restrict__ dattr,
                              const float* __restrict__ Wpos, const float* __restrict__ bpos,
                              const float* __restrict__ Wdom, const float* __restrict__ bdom) {
    long long gid = (long long)blockIdx.x * blockDim.x + threadIdx.x;
    long long eg = gid >> 1;
    int sub = (int)(gid & 1);      // half: proj channels [sub*16,+16), mask [sub*8,+8)
    if (eg >= (long long)(ES + ED)) return;

    bool spatial = (eg < ES);
    int e = spatial ? (int)eg : (int)(eg - ES);
    const int* eidx = spatial ? si : di;
    int nE = spatial ? ES : ED;
    int src = eidx[e];
    int dst = eidx[nE + e];

    const __half* arow = &g_A[(size_t)src * NSTR];
    const __half* brow = &g_B[(size_t)dst * NSTR];
    uint4 pa0 = *reinterpret_cast<const uint4*>(arow + sub * 16);
    uint4 pa1 = *reinterpret_cast<const uint4*>(arow + sub * 16 + 8);
    uint4 pb0 = *reinterpret_cast<const uint4*>(brow + sub * 16);
    uint4 pb1 = *reinterpret_cast<const uint4*>(brow + sub * 16 + 8);
    uint4 sr  = *reinterpret_cast<const uint4*>(arow + TT + sub * 8);  // src mask16
    uint4 dr  = *reinterpret_cast<const uint4*>(brow + TT + sub * 8);  // dst mask16

    const __half2* ph0 = reinterpret_cast<const __half2*>(&pa0);
    const __half2* ph1 = reinterpret_cast<const __half2*>(&pa1);
    const __half2* qh0 = reinterpret_cast<const __half2*>(&pb0);
    const __half2* qh1 = reinterpret_cast<const __half2*>(&pb1);

    float th[16];
#pragma unroll
    for (int j = 0; j < 4; j++) {
        float2 a = __half22float2(ph0[j]);
        float2 b = __half22float2(qh0[j]);
        th[2 * j]     = fast_tanh(a.x + b.x);
        th[2 * j + 1] = fast_tanh(a.y + b.y);
        float2 c = __half22float2(ph1[j]);
        float2 d = __half22float2(qh1[j]);
        th[8 + 2 * j]     = fast_tanh(c.x + d.x);
        th[8 + 2 * j + 1] = fast_tanh(c.y + d.y);
    }

    float part = 0.f;
    if (spatial) {
        const float* w = &Wpos[4 + sub * 16];
#pragma unroll
        for (int j = 0; j < 16; j++) part += th[j] * w[j];
        if (sub == 0) {
            float4 a = *reinterpret_cast<const float4*>(&sattr[(size_t)e * 4]);
            part += a.x * Wpos[0] + a.y * Wpos[1] + a.z * Wpos[2] + a.w * Wpos[3];
        }
    } else {
        const float* w = &Wdom[1 + sub * 16];
#pragma unroll
        for (int j = 0; j < 16; j++) part += th[j] * w[j];
        if (sub == 0) part += dattr[e] * Wdom[0];
    }

    part += __shfl_xor_sync(0xFFFFFFFFu, part, 1);

    float logit = part + (spatial ? bpos[0] : bdom[0]);
    float ew = 1.f / (1.f + __expf(-logit));
    if (sub == 0) { if (spatial) g_ew_s[e] = ew; else g_ew_d[e] = ew; }

    // ---- fused round-1 propagation: 2 lanes x 8 channels ----
    {
        float* n = spatial ? g_n32pos : g_n32dom;
        const __half2* sh = reinterpret_cast<const __half2*>(&sr);
        const __half2* dh = reinterpret_cast<const __half2*>(&dr);
        unsigned int* dn = reinterpret_cast<unsigned int*>(&n[(size_t)dst * MDIM + sub * 8]);
#pragma unroll
        for (int j = 0; j < 4; j++) {
            float2 s = __half22float2(sh[j]);
            float2 d = __half22float2(dh[j]);
            float v0 = s.x * ew, v1 = s.y * ew;
            if (v0 > d.x) atomicMax(dn + 2 * j + 0, __float_as_uint(v0));
            if (v1 > d.y) atomicMax(dn + 2 * j + 1, __float_as_uint(v1));
        }
    }
}

// ---------------- kernel 3: convert n32 -> compact c16 mirrors -------------
__global__ void convert_kernel() {
    int i = blockIdx.x * blockDim.x + threadIdx.x;
    const int n4 = NN * MDIM / 4;
    if (i >= n4) return;
    float4 p = reinterpret_cast<const float4*>(g_n32pos)[i];
    float4 d = reinterpret_cast<const float4*>(g_n32dom)[i];
    __half2 p0 = __floats2half2_rn(p.x, p.y);
    __half2 p1 = __floats2half2_rn(p.z, p.w);
    __half2 d0 = __floats2half2_rn(d.x, d.y);
    __half2 d1 = __floats2half2_rn(d.z, d.w);
    reinterpret_cast<uint2*>(g_c16pos)[i] =
        make_uint2(*reinterpret_cast<unsigned*>(&p0), *reinterpret_cast<unsigned*>(&p1));
    reinterpret_cast<uint2*>(g_c16dom)[i] =
        make_uint2(*reinterpret_cast<unsigned*>(&d0), *reinterpret_cast<unsigned*>(&d1));
}

// ---------------- kernel 4: propagation rounds 2-3 -------------------------
__global__ void prop_kernel(const int* __restrict__ si, const int* __restrict__ di) {
    long long t = (long long)blockIdx.x * blockDim.x + threadIdx.x;
    if (t >= (long long)ES * 2) return;
    int p = (int)(t >> 1);       // edge id in each set
    int sub = (int)(t & 1);      // half-row (8 channels)

    int s0 = si[p], d0 = si[ES + p];
    int s1 = di[p], d1 = di[ED + p];
    float ew0 = g_ew_s[p];
    float ew1 = g_ew_d[p];

    uint4 sr0 = *reinterpret_cast<const uint4*>(&g_c16pos[(size_t)s0 * MDIM + sub * 8]);
    uint4 dr0 = *reinterpret_cast<const uint4*>(&g_c16pos[(size_t)d0 * MDIM + sub * 8]);
    uint4 sr1 = *reinterpret_cast<const uint4*>(&g_c16dom[(size_t)s1 * MDIM + sub * 8]);
    uint4 dr1 = *reinterpret_cast<const uint4*>(&g_c16dom[(size_t)d1 * MDIM + sub * 8]);

    {
        const __half2* sh = reinterpret_cast<const __half2*>(&sr0);
        const __half2* dh = reinterpret_cast<const __half2*>(&dr0);
        unsigned int* dn = reinterpret_cast<unsigned int*>(&g_n32pos[(size_t)d0 * MDIM + sub * 8]);
#pragma unroll
        for (int j = 0; j < 4; j++) {
            float2 s = __half22float2(sh[j]);
            float2 d = __half22float2(dh[j]);
            float v0 = s.x * ew0, v1 = s.y * ew0;
            if (v0 > d.x) atomicMax(dn + 2 * j + 0, __float_as_uint(v0));
            if (v1 > d.y) atomicMax(dn + 2 * j + 1, __float_as_uint(v1));
        }
    }
    {
        const __half2* sh = reinterpret_cast<const __half2*>(&sr1);
        const __half2* dh = reinterpret_cast<const __half2*>(&dr1);
        unsigned int* dn = reinterpret_cast<unsigned int*>(&g_n32dom[(size_t)d1 * MDIM + sub * 8]);
#pragma unroll
        for (int j = 0; j < 4; j++) {
            float2 s = __half22float2(sh[j]);
            float2 d = __half22float2(dh[j]);
            float v0 = s.x * ew1, v1 = s.y * ew1;
            if (v0 > d.x) atomicMax(dn + 2 * j + 0, __float_as_uint(v0));
            if (v1 > d.y) atomicMax(dn + 2 * j + 1, __float_as_uint(v1));
        }
    }
}

// ---------------- kernel 5: final max --------------------------------------
__global__ void final_kernel(const float* __restrict__ mask, float* __restrict__ out) {
    int i = blockIdx.x * blockDim.x + threadIdx.x;
    const int n4 = NN * MDIM / 4;
    if (i >= n4) return;
    float4 m = reinterpret_cast<const float4*>(mask)[i];
    float4 p = reinterpret_cast<const float4*>(g_n32pos)[i];
    float4 d = reinterpret_cast<const float4*>(g_n32dom)[i];
    float4 r;
    r.x = fmaxf(m.x, fmaxf(p.x, d.x));
    r.y = fmaxf(m.y, fmaxf(p.y, d.y));
    r.z = fmaxf(m.z, fmaxf(p.z, d.z));
    r.w = fmaxf(m.w, fmaxf(p.w, d.w));
    reinterpret_cast<float4*>(out)[i] = r;
}

// ---------------- launch -------------------------------------------------
extern "C" void kernel_launch(void* const* d_in, const int* in_sizes, int n_in,
                              void* d_out, int out_size) {
    const float* x     = (const float*)d_in[0];
    const float* mask  = (const float*)d_in[1];
    const int*   si    = (const int*)d_in[2];
    const int*   di    = (const int*)d_in[3];
    const float* sattr = (const float*)d_in[4];
    const float* dattr = (const float*)d_in[5];
    const float* Wt    = (const float*)d_in[6];
    const float* bt    = (const float*)d_in[7];
    const float* Wpos  = (const float*)d_in[8];
    const float* bpos  = (const float*)d_in[9];
    const float* Wdom  = (const float*)d_in[10];
    const float* bdom  = (const float*)d_in[11];
    float* out = (float*)d_out;

    const int n4 = NN * MDIM / 4;
    const int cgrid = (n4 + 255) / 256;

    // 1. HMMA node projections + fused init (interleaved tables)
    proj_kernel<<<(NN + 63) / 64, 128>>>(x, Wt, bt, mask);

    // 2. fused gate + propagation round 1 (2 lanes/edge, 1 line per endpoint)
    {
        long long threads = (long long)(ES + ED) * 2;
        int blk = 256;
        long long grid = (threads + blk - 1) / blk;
        ewprop_kernel<<<(unsigned)grid, blk>>>(si, di, sattr, dattr, Wpos, bpos, Wdom, bdom);
    }

    // 3. rounds 2-3: convert / prop / convert / prop
    {
        long long threads = (long long)ES * 2;
        int blk = 256;
        long long grid = (threads + blk - 1) / blk;

        convert_kernel<<<cgrid, 256>>>();
        prop_kernel<<<(unsigned)grid, blk>>>(si, di);
        convert_kernel<<<cgrid, 256>>>();
        prop_kernel<<<(unsigned)grid, blk>>>(si, di);
    }

    // 4. final: max(mask, pos, dom)
    final_kernel<<<cgrid, 256>>>(mask, out);
}

// round 14
// speedup vs baseline: 1.0851x; 1.0851x over previous
#include <cuda_runtime.h>
#include <cuda_fp16.h>
#include <cstdint>

#define NN     100000
#define HH     128
#define TT     32
#define MDIM   16
#define ES     600000
#define ED     600000

// ---------------- scratch ----------------
__device__ __align__(16) __half g_Ps[NN * TT];   // fp16 x@W[:H]
__device__ __align__(16) __half g_Pd[NN * TT];   // fp16 x@W[H:] + b_trans
__device__ float g_ew_s[ES];
__device__ float g_ew_d[ED];
// propagation state: fp32 accumulator (atomics) + fp16 read mirror
__device__ __align__(16) float  g_n32pos[NN * MDIM];
__device__ __align__(16) float  g_n32dom[NN * MDIM];
__device__ __align__(16) __half g_c16pos[NN * MDIM];
__device__ __align__(16) __half g_c16dom[NN * MDIM];

// ---------------- helpers ----------------
__device__ __forceinline__ float fast_tanh(float s) {
    float r; asm("tanh.approx.f32 %0, %1;" : "=f"(r) : "f"(s)); return r;
}
__device__ __forceinline__ unsigned su32(const void* p) {
    return (unsigned)__cvta_generic_to_shared(p);
}

// ---------------- kernel 1: HMMA node projections + fused init -------------
#define XS_STRIDE 136
#define WP_STRIDE 72

__global__ void __launch_bounds__(128) proj_kernel(const float* __restrict__ x,
                                                   const float* __restrict__ Wt,
                                                   const float* __restrict__ bt,
                                                   const float* __restrict__ mask) {
    __shared__ __align__(16) __half Wp[128 * WP_STRIDE];
    __shared__ __align__(16) __half xs[64 * XS_STRIDE];
    int tid = threadIdx.x;
    int n0 = blockIdx.x * 64;

    // ---- fused init: mask -> n32 (fp32) + c16 (fp16), grid-stride ----
    {
        const int n4 = NN * MDIM / 4;
        for (int i = blockIdx.x * 128 + tid; i < n4; i += gridDim.x * 128) {
            float4 v = reinterpret_cast<const float4*>(mask)[i];
            reinterpret_cast<float4*>(g_n32pos)[i] = v;
            reinterpret_cast<float4*>(g_n32dom)[i] = v;
            __half2 h0 = __floats2half2_rn(v.x, v.y);
            __half2 h1 = __floats2half2_rn(v.z, v.w);
            uint2 packed = make_uint2(*reinterpret_cast<unsigned*>(&h0),
                                      *reinterpret_cast<unsigned*>(&h1));
            reinterpret_cast<uint2*>(g_c16pos)[i] = packed;
            reinterpret_cast<uint2*>(g_c16dom)[i] = packed;
        }
    }

    for (int i = tid; i < 128 * 64; i += 128) {
        int h = i >> 6, j = i & 63;
        float w = (j < 32) ? Wt[h * 32 + j] : Wt[(128 + h) * 32 + (j - 32)];
        Wp[h * WP_STRIDE + j] = __float2half_rn(w);
    }
    for (int i = tid; i < 64 * 32; i += 128) {
        int r = i >> 5, c4 = i & 31;
        int node = n0 + r;
        float4 v = (node < NN)
                 ? reinterpret_cast<const float4*>(x)[(size_t)node * 32 + c4]
                 : make_float4(0.f, 0.f, 0.f, 0.f);
        *reinterpret_cast<__half2*>(&xs[r * XS_STRIDE + c4 * 4])     = __floats2half2_rn(v.x, v.y);
        *reinterpret_cast<__half2*>(&xs[r * XS_STRIDE + c4 * 4 + 2]) = __floats2half2_rn(v.z, v.w);
    }
    __syncthreads();

    int warp = tid >> 5, lane = tid & 31;
    int wb = warp * 16;

    float acc[8][4];
#pragma unroll
    for (int nt = 0; nt < 8; nt++)
#pragma unroll
        for (int j = 0; j < 4; j++) acc[nt][j] = 0.f;

    int a_row = wb + (lane & 15);
    int a_coff = (lane >> 4) * 8;
    int b_row = (lane & 15);

#pragma unroll
    for (int k = 0; k < 8; k++) {
        unsigned a0, a1, a2, a3;
        unsigned addrA = su32(&xs[a_row * XS_STRIDE + k * 16 + a_coff]);
        asm volatile("ldmatrix.sync.aligned.m8n8.x4.shared.b16 {%0,%1,%2,%3}, [%4];"
                     : "=r"(a0), "=r"(a1), "=r"(a2), "=r"(a3) : "r"(addrA));
#pragma unroll
        for (int nt = 0; nt < 8; nt++) {
            unsigned b0, b1;
            unsigned addrB = su32(&Wp[(k * 16 + b_row) * WP_STRIDE + nt * 8]);
            asm volatile("ldmatrix.sync.aligned.m8n8.x2.trans.shared.b16 {%0,%1}, [%2];"
                         : "=r"(b0), "=r"(b1) : "r"(addrB));
            asm volatile("mma.sync.aligned.m16n8k16.row.col.f32.f16.f16.f32 "
                         "{%0,%1,%2,%3}, {%4,%5,%6,%7}, {%8,%9}, {%0,%1,%2,%3};"
                         : "+f"(acc[nt][0]), "+f"(acc[nt][1]), "+f"(acc[nt][2]), "+f"(acc[nt][3])
                         : "r"(a0), "r"(a1), "r"(a2), "r"(a3), "r"(b0), "r"(b1));
        }
    }

    int row_l = wb + (lane >> 2);
    int col0 = (lane & 3) * 2;
#pragma unroll
    for (int nt = 0; nt < 8; nt++) {
        bool isPs = (nt < 4);
        __half* base = isPs ? g_Ps : g_Pd;
        int cc = isPs ? (nt * 8 + col0) : (nt * 8 + col0 - 32);
        float b0 = isPs ? 0.f : bt[cc];
        float b1 = isPs ? 0.f : bt[cc + 1];
        int nodeA = n0 + row_l;
        int nodeB = nodeA + 8;
        if (nodeA < NN)
            *reinterpret_cast<__half2*>(&base[(size_t)nodeA * TT + cc]) =
                __floats2half2_rn(acc[nt][0] + b0, acc[nt][1] + b1);
        if (nodeB < NN)
            *reinterpret_cast<__half2*>(&base[(size_t)nodeB * TT + cc]) =
                __floats2half2_rn(acc[nt][2] + b0, acc[nt][3] + b1);
    }
}

// ---------------- kernel 2: FUSED gate + propagation round 1 ---------------
// 2 lanes/edge. Filter now tests against the LIVE fp32 accumulator (only
// grows; any past value is a safe conservative bound) -> strictly stronger
// filter than the frozen fp16 mirror, same request count.
__global__ void ewprop_kernel(const int* __restrict__ si, const int* __restrict__ di,
                              const float* __restrict__ sattr, const float* __restrict__ dattr,
                              const float* __restrict__ Wpos, const float* __restrict__ bpos,
                              const float* __restrict__ Wdom, const float* __restrict__ bdom) {
    long long gid = (long long)blockIdx.x * blockDim.x + threadIdx.x;
    long long eg = gid >> 1;
    int sub = (int)(gid & 1);      // half: channels [sub*16, sub*16+16)
    if (eg >= (long long)(ES + ED)) return;

    bool spatial = (eg < ES);
    int e = spatial ? (int)eg : (int)(eg - ES);
    const int* eidx = spatial ? si : di;
    int nE = spatial ? ES : ED;
    int src = eidx[e];
    int dst = eidx[nE + e];

    const __half* psrow = &g_Ps[(size_t)src * TT + sub * 16];
    const __half* pdrow = &g_Pd[(size_t)dst * TT + sub * 16];
    uint4 pa0 = *reinterpret_cast<const uint4*>(psrow);
    uint4 pa1 = *reinterpret_cast<const uint4*>(psrow + 8);
    uint4 pb0 = *reinterpret_cast<const uint4*>(pdrow);
    uint4 pb1 = *reinterpret_cast<const uint4*>(pdrow + 8);
    const __half2* ph0 = reinterpret_cast<const __half2*>(&pa0);
    const __half2* ph1 = reinterpret_cast<const __half2*>(&pa1);
    const __half2* qh0 = reinterpret_cast<const __half2*>(&pb0);
    const __half2* qh1 = reinterpret_cast<const __half2*>(&pb1);

    float th[16];
#pragma unroll
    for (int j = 0; j < 4; j++) {
        float2 a = __half22float2(ph0[j]);
        float2 b = __half22float2(qh0[j]);
        th[2 * j]     = fast_tanh(a.x + b.x);
        th[2 * j + 1] = fast_tanh(a.y + b.y);
        float2 c = __half22float2(ph1[j]);
        float2 d = __half22float2(qh1[j]);
        th[8 + 2 * j]     = fast_tanh(c.x + d.x);
        th[8 + 2 * j + 1] = fast_tanh(c.y + d.y);
    }

    float part = 0.f;
    if (spatial) {
        const float* w = &Wpos[4 + sub * 16];
#pragma unroll
        for (int j = 0; j < 16; j++) part += th[j] * w[j];
        if (sub == 0) {
            float4 a = *reinterpret_cast<const float4*>(&sattr[(size_t)e * 4]);
            part += a.x * Wpos[0] + a.y * Wpos[1] + a.z * Wpos[2] + a.w * Wpos[3];
        }
    } else {
        const float* w = &Wdom[1 + sub * 16];
#pragma unroll
        for (int j = 0; j < 16; j++) part += th[j] * w[j];
        if (sub == 0) part += dattr[e] * Wdom[0];
    }

    part += __shfl_xor_sync(0xFFFFFFFFu, part, 1);

    float logit = part + (spatial ? bpos[0] : bdom[0]);
    float ew = 1.f / (1.f + __expf(-logit));
    if (sub == 0) { if (spatial) g_ew_s[e] = ew; else g_ew_d[e] = ew; }

    // ---- fused round-1 propagation: 2 lanes x 8 channels, live filter ----
    {
        const __half* c = spatial ? g_c16pos : g_c16dom;
        float* n = spatial ? g_n32pos : g_n32dom;
        uint4 sr = *reinterpret_cast<const uint4*>(&c[(size_t)src * MDIM + sub * 8]);
        const float4* drow = reinterpret_cast<const float4*>(&n[(size_t)dst * MDIM + sub * 8]);
        float4 dA = drow[0], dB = drow[1];
        const __half2* sh = reinterpret_cast<const __half2*>(&sr);
        unsigned int* dn = reinterpret_cast<unsigned int*>(&n[(size_t)dst * MDIM + sub * 8]);
        float dv[8] = {dA.x, dA.y, dA.z, dA.w, dB.x, dB.y, dB.z, dB.w};
#pragma unroll
        for (int j = 0; j < 4; j++) {
            float2 s = __half22float2(sh[j]);
            float v0 = s.x * ew, v1 = s.y * ew;
            if (v0 > dv[2 * j])     atomicMax(dn + 2 * j + 0, __float_as_uint(v0));
            if (v1 > dv[2 * j + 1]) atomicMax(dn + 2 * j + 1, __float_as_uint(v1));
        }
    }
}

// ---------------- kernel 3: convert n32 -> c16 (both branches) ------------
__global__ void convert_kernel() {
    int i = blockIdx.x * blockDim.x + threadIdx.x;
    const int n4 = NN * MDIM / 4;
    if (i >= n4) return;
    float4 p = reinterpret_cast<const float4*>(g_n32pos)[i];
    float4 d = reinterpret_cast<const float4*>(g_n32dom)[i];
    __half2 p0 = __floats2half2_rn(p.x, p.y);
    __half2 p1 = __floats2half2_rn(p.z, p.w);
    __half2 d0 = __floats2half2_rn(d.x, d.y);
    __half2 d1 = __floats2half2_rn(d.z, d.w);
    reinterpret_cast<uint2*>(g_c16pos)[i] =
        make_uint2(*reinterpret_cast<unsigned*>(&p0), *reinterpret_cast<unsigned*>(&p1));
    reinterpret_cast<uint2*>(g_c16dom)[i] =
        make_uint2(*reinterpret_cast<unsigned*>(&d0), *reinterpret_cast<unsigned*>(&d1));
}

// ---------------- kernel 4: propagation rounds 2-3 (live filter) -----------
__global__ void prop_kernel(const int* __restrict__ si, const int* __restrict__ di) {
    long long t = (long long)blockIdx.x * blockDim.x + threadIdx.x;
    if (t >= (long long)ES * 2) return;
    int p = (int)(t >> 1);       // edge id in each set
    int sub = (int)(t & 1);      // half-row (8 channels)

    int s0 = si[p], d0 = si[ES + p];
    int s1 = di[p], d1 = di[ED + p];
    float ew0 = g_ew_s[p];
    float ew1 = g_ew_d[p];

    // front-batched: 2 src mirror rows + 2 live dst rows (MLP 4+)
    uint4 sr0 = *reinterpret_cast<const uint4*>(&g_c16pos[(size_t)s0 * MDIM + sub * 8]);
    uint4 sr1 = *reinterpret_cast<const uint4*>(&g_c16dom[(size_t)s1 * MDIM + sub * 8]);
    const float4* dr0p = reinterpret_cast<const float4*>(&g_n32pos[(size_t)d0 * MDIM + sub * 8]);
    const float4* dr1p = reinterpret_cast<const float4*>(&g_n32dom[(size_t)d1 * MDIM + sub * 8]);
    float4 d0A = dr0p[0], d0B = dr0p[1];
    float4 d1A = dr1p[0], d1B = dr1p[1];

    {
        const __half2* sh = reinterpret_cast<const __half2*>(&sr0);
        unsigned int* dn = reinterpret_cast<unsigned int*>(&g_n32pos[(size_t)d0 * MDIM + sub * 8]);
        float dv[8] = {d0A.x, d0A.y, d0A.z, d0A.w, d0B.x, d0B.y, d0B.z, d0B.w};
#pragma unroll
        for (int j = 0; j < 4; j++) {
            float2 s = __half22float2(sh[j]);
            float v0 = s.x * ew0, v1 = s.y * ew0;
            if (v0 > dv[2 * j])     atomicMax(dn + 2 * j + 0, __float_as_uint(v0));
            if (v1 > dv[2 * j + 1]) atomicMax(dn + 2 * j + 1, __float_as_uint(v1));
        }
    }
    {
        const __half2* sh = reinterpret_cast<const __half2*>(&sr1);
        unsigned int* dn = reinterpret_cast<unsigned int*>(&g_n32dom[(size_t)d1 * MDIM + sub * 8]);
        float dv[8] = {d1A.x, d1A.y, d1A.z, d1A.w, d1B.x, d1B.y, d1B.z, d1B.w};
#pragma unroll
        for (int j = 0; j < 4; j++) {
            float2 s = __half22float2(sh[j]);
            float v0 = s.x * ew1, v1 = s.y * ew1;
            if (v0 > dv[2 * j])     atomicMax(dn + 2 * j + 0, __float_as_uint(v0));
            if (v1 > dv[2 * j + 1]) atomicMax(dn + 2 * j + 1, __float_as_uint(v1));
        }
    }
}

// ---------------- kernel 5: final max --------------------------------------
__global__ void final_kernel(const float* __restrict__ mask, float* __restrict__ out) {
    int i = blockIdx.x * blockDim.x + threadIdx.x;
    const int n4 = NN * MDIM / 4;
    if (i >= n4) return;
    float4 m = reinterpret_cast<const float4*>(mask)[i];
    float4 p = reinterpret_cast<const float4*>(g_n32pos)[i];
    float4 d = reinterpret_cast<const float4*>(g_n32dom)[i];
    float4 r;
    r.x = fmaxf(m.x, fmaxf(p.x, d.x));
    r.y = fmaxf(m.y, fmaxf(p.y, d.y));
    r.z = fmaxf(m.z, fmaxf(p.z, d.z));
    r.w = fmaxf(m.w, fmaxf(p.w, d.w));
    reinterpret_cast<float4*>(out)[i] = r;
}

// ---------------- launch -------------------------------------------------
extern "C" void kernel_launch(void* const* d_in, const int* in_sizes, int n_in,
                              void* d_out, int out_size) {
    const float* x     = (const float*)d_in[0];
    const float* mask  = (const float*)d_in[1];
    const int*   si    = (const int*)d_in[2];
    const int*   di    = (const int*)d_in[3];
    const float* sattr = (const float*)d_in[4];
    const float* dattr = (const float*)d_in[5];
    const float* Wt    = (const float*)d_in[6];
    const float* bt    = (const float*)d_in[7];
    const float* Wpos  = (const float*)d_in[8];
    const float* bpos  = (const float*)d_in[9];
    const float* Wdom  = (const float*)d_in[10];
    const float* bdom  = (const float*)d_in[11];
    float* out = (float*)d_out;

    const int n4 = NN * MDIM / 4;
    const int cgrid = (n4 + 255) / 256;

    // 1. HMMA node projections + fused mask-buffer init
    proj_kernel<<<(NN + 63) / 64, 128>>>(x, Wt, bt, mask);

    // 2. fused gate + propagation round 1 (2 lanes/edge)
    {
        long long threads = (long long)(ES + ED) * 2;
        int blk = 256;
        long long grid = (threads + blk - 1) / blk;
        ewprop_kernel<<<(unsigned)grid, blk>>>(si, di, sattr, dattr, Wpos, bpos, Wdom, bdom);
    }

    // 3. rounds 2-3: convert / prop / convert / prop
    {
        long long threads = (long long)ES * 2;   // 2 edges (one per set) per thread
        int blk = 256;
        long long grid = (threads + blk - 1) / blk;

        convert_kernel<<<cgrid, 256>>>();
        prop_kernel<<<(unsigned)grid, blk>>>(si, di);
        convert_kernel<<<cgrid, 256>>>();
        prop_kernel<<<(unsigned)grid, blk>>>(si, di);
    }

    // 4. final: max(mask, pos, dom)
    final_kernel<<<cgrid, 256>>>(mask, out);
}

// round 15
// speedup vs baseline: 1.0859x; 1.0008x over previous
#include <cuda_runtime.h>
#include <cuda_fp16.h>
#include <cstdint>

#define NN     100000
#define HH     128
#define TT     32
#define MDIM   16
#define ES     600000
#define ED     600000

// ---------------- scratch ----------------
__device__ __align__(16) __half g_Ps[NN * TT];   // fp16 x@W[:H]
__device__ __align__(16) __half g_Pd[NN * TT];   // fp16 x@W[H:] + b_trans
__device__ float g_ew_s[ES];
__device__ float g_ew_d[ED];
// propagation state: fp32 accumulator (atomics) + fp16 read mirror
__device__ __align__(16) float  g_n32pos[NN * MDIM];
__device__ __align__(16) float  g_n32dom[NN * MDIM];
__device__ __align__(16) __half g_c16pos[NN * MDIM];
__device__ __align__(16) __half g_c16dom[NN * MDIM];

// ---------------- helpers ----------------
__device__ __forceinline__ float fast_tanh(float s) {
    float r; asm("tanh.approx.f32 %0, %1;" : "=f"(r) : "f"(s)); return r;
}
__device__ __forceinline__ unsigned su32(const void* p) {
    return (unsigned)__cvta_generic_to_shared(p);
}

// ---------------- kernel 1: HMMA node projections + fused init -------------
#define XS_STRIDE 136
#define WP_STRIDE 72

__global__ void __launch_bounds__(128) proj_kernel(const float* __restrict__ x,
                                                   const float* __restrict__ Wt,
                                                   const float* __restrict__ bt,
                                                   const float* __restrict__ mask) {
    __shared__ __align__(16) __half Wp[128 * WP_STRIDE];
    __shared__ __align__(16) __half xs[64 * XS_STRIDE];
    int tid = threadIdx.x;
    int n0 = blockIdx.x * 64;

    // ---- fused init: mask -> n32 (fp32) + c16 (fp16), grid-stride ----
    {
        const int n4 = NN * MDIM / 4;
        for (int i = blockIdx.x * 128 + tid; i < n4; i += gridDim.x * 128) {
            float4 v = reinterpret_cast<const float4*>(mask)[i];
            reinterpret_cast<float4*>(g_n32pos)[i] = v;
            reinterpret_cast<float4*>(g_n32dom)[i] = v;
            __half2 h0 = __floats2half2_rn(v.x, v.y);
            __half2 h1 = __floats2half2_rn(v.z, v.w);
            uint2 packed = make_uint2(*reinterpret_cast<unsigned*>(&h0),
                                      *reinterpret_cast<unsigned*>(&h1));
            reinterpret_cast<uint2*>(g_c16pos)[i] = packed;
            reinterpret_cast<uint2*>(g_c16dom)[i] = packed;
        }
    }

    for (int i = tid; i < 128 * 64; i += 128) {
        int h = i >> 6, j = i & 63;
        float w = (j < 32) ? Wt[h * 32 + j] : Wt[(128 + h) * 32 + (j - 32)];
        Wp[h * WP_STRIDE + j] = __float2half_rn(w);
    }
    for (int i = tid; i < 64 * 32; i += 128) {
        int r = i >> 5, c4 = i & 31;
        int node = n0 + r;
        float4 v = (node < NN)
                 ? reinterpret_cast<const float4*>(x)[(size_t)node * 32 + c4]
                 : make_float4(0.f, 0.f, 0.f, 0.f);
        *reinterpret_cast<__half2*>(&xs[r * XS_STRIDE + c4 * 4])     = __floats2half2_rn(v.x, v.y);
        *reinterpret_cast<__half2*>(&xs[r * XS_STRIDE + c4 * 4 + 2]) = __floats2half2_rn(v.z, v.w);
    }
    __syncthreads();

    int warp = tid >> 5, lane = tid & 31;
    int wb = warp * 16;

    float acc[8][4];
#pragma unroll
    for (int nt = 0; nt < 8; nt++)
#pragma unroll
        for (int j = 0; j < 4; j++) acc[nt][j] = 0.f;

    int a_row = wb + (lane & 15);
    int a_coff = (lane >> 4) * 8;
    int b_row = (lane & 15);

#pragma unroll
    for (int k = 0; k < 8; k++) {
        unsigned a0, a1, a2, a3;
        unsigned addrA = su32(&xs[a_row * XS_STRIDE + k * 16 + a_coff]);
        asm volatile("ldmatrix.sync.aligned.m8n8.x4.shared.b16 {%0,%1,%2,%3}, [%4];"
                     : "=r"(a0), "=r"(a1), "=r"(a2), "=r"(a3) : "r"(addrA));
#pragma unroll
        for (int nt = 0; nt < 8; nt++) {
            unsigned b0, b1;
            unsigned addrB = su32(&Wp[(k * 16 + b_row) * WP_STRIDE + nt * 8]);
            asm volatile("ldmatrix.sync.aligned.m8n8.x2.trans.shared.b16 {%0,%1}, [%2];"
                         : "=r"(b0), "=r"(b1) : "r"(addrB));
            asm volatile("mma.sync.aligned.m16n8k16.row.col.f32.f16.f16.f32 "
                         "{%0,%1,%2,%3}, {%4,%5,%6,%7}, {%8,%9}, {%0,%1,%2,%3};"
                         : "+f"(acc[nt][0]), "+f"(acc[nt][1]), "+f"(acc[nt][2]), "+f"(acc[nt][3])
                         : "r"(a0), "r"(a1), "r"(a2), "r"(a3), "r"(b0), "r"(b1));
        }
    }

    int row_l = wb + (lane >> 2);
    int col0 = (lane & 3) * 2;
#pragma unroll
    for (int nt = 0; nt < 8; nt++) {
        bool isPs = (nt < 4);
        __half* base = isPs ? g_Ps : g_Pd;
        int cc = isPs ? (nt * 8 + col0) : (nt * 8 + col0 - 32);
        float b0 = isPs ? 0.f : bt[cc];
        float b1 = isPs ? 0.f : bt[cc + 1];
        int nodeA = n0 + row_l;
        int nodeB = nodeA + 8;
        if (nodeA < NN)
            *reinterpret_cast<__half2*>(&base[(size_t)nodeA * TT + cc]) =
                __floats2half2_rn(acc[nt][0] + b0, acc[nt][1] + b1);
        if (nodeB < NN)
            *reinterpret_cast<__half2*>(&base[(size_t)nodeB * TT + cc]) =
                __floats2half2_rn(acc[nt][2] + b0, acc[nt][3] + b1);
    }
}

// ---------------- kernel 2: FUSED gate + propagation round 1 ---------------
// 2 lanes/edge; live-accumulator filter (proven win in R14), direct float4
// compares to keep register pressure down.
__global__ void ewprop_kernel(const int* __restrict__ si, const int* __restrict__ di,
                              const float* __restrict__ sattr, const float* __restrict__ dattr,
                              const float* __restrict__ Wpos, const float* __restrict__ bpos,
                              const float* __restrict__ Wdom, const float* __restrict__ bdom) {
    long long gid = (long long)blockIdx.x * blockDim.x + threadIdx.x;
    long long eg = gid >> 1;
    int sub = (int)(gid & 1);      // half: channels [sub*16, sub*16+16)
    if (eg >= (long long)(ES + ED)) return;

    bool spatial = (eg < ES);
    int e = spatial ? (int)eg : (int)(eg - ES);
    const int* eidx = spatial ? si : di;
    int nE = spatial ? ES : ED;
    int src = eidx[e];
    int dst = eidx[nE + e];

    const __half* psrow = &g_Ps[(size_t)src * TT + sub * 16];
    const __half* pdrow = &g_Pd[(size_t)dst * TT + sub * 16];
    uint4 pa0 = *reinterpret_cast<const uint4*>(psrow);
    uint4 pa1 = *reinterpret_cast<const uint4*>(psrow + 8);
    uint4 pb0 = *reinterpret_cast<const uint4*>(pdrow);
    uint4 pb1 = *reinterpret_cast<const uint4*>(pdrow + 8);
    const __half2* ph0 = reinterpret_cast<const __half2*>(&pa0);
    const __half2* ph1 = reinterpret_cast<const __half2*>(&pa1);
    const __half2* qh0 = reinterpret_cast<const __half2*>(&pb0);
    const __half2* qh1 = reinterpret_cast<const __half2*>(&pb1);

    float th[16];
#pragma unroll
    for (int j = 0; j < 4; j++) {
        float2 a = __half22float2(ph0[j]);
        float2 b = __half22float2(qh0[j]);
        th[2 * j]     = fast_tanh(a.x + b.x);
        th[2 * j + 1] = fast_tanh(a.y + b.y);
        float2 c = __half22float2(ph1[j]);
        float2 d = __half22float2(qh1[j]);
        th[8 + 2 * j]     = fast_tanh(c.x + d.x);
        th[8 + 2 * j + 1] = fast_tanh(c.y + d.y);
    }

    float part = 0.f;
    if (spatial) {
        const float* w = &Wpos[4 + sub * 16];
#pragma unroll
        for (int j = 0; j < 16; j++) part += th[j] * w[j];
        if (sub == 0) {
            float4 a = *reinterpret_cast<const float4*>(&sattr[(size_t)e * 4]);
            part += a.x * Wpos[0] + a.y * Wpos[1] + a.z * Wpos[2] + a.w * Wpos[3];
        }
    } else {
        const float* w = &Wdom[1 + sub * 16];
#pragma unroll
        for (int j = 0; j < 16; j++) part += th[j] * w[j];
        if (sub == 0) part += dattr[e] * Wdom[0];
    }

    part += __shfl_xor_sync(0xFFFFFFFFu, part, 1);

    float logit = part + (spatial ? bpos[0] : bdom[0]);
    float ew = 1.f / (1.f + __expf(-logit));
    if (sub == 0) { if (spatial) g_ew_s[e] = ew; else g_ew_d[e] = ew; }

    // ---- fused round-1 propagation: 2 lanes x 8 channels, live filter ----
    {
        const __half* c = spatial ? g_c16pos : g_c16dom;
        float* n = spatial ? g_n32pos : g_n32dom;
        uint4 sr = *reinterpret_cast<const uint4*>(&c[(size_t)src * MDIM + sub * 8]);
        const float4* drow = reinterpret_cast<const float4*>(&n[(size_t)dst * MDIM + sub * 8]);
        float4 dA = drow[0], dB = drow[1];
        const __half2* sh = reinterpret_cast<const __half2*>(&sr);
        unsigned int* dn = reinterpret_cast<unsigned int*>(&n[(size_t)dst * MDIM + sub * 8]);

        float2 s0 = __half22float2(sh[0]);
        float2 s1 = __half22float2(sh[1]);
        float2 s2 = __half22float2(sh[2]);
        float2 s3 = __half22float2(sh[3]);
        float v0 = s0.x * ew, v1 = s0.y * ew, v2 = s1.x * ew, v3 = s1.y * ew;
        float v4 = s2.x * ew, v5 = s2.y * ew, v6 = s3.x * ew, v7 = s3.y * ew;
        if (v0 > dA.x) atomicMax(dn + 0, __float_as_uint(v0));
        if (v1 > dA.y) atomicMax(dn + 1, __float_as_uint(v1));
        if (v2 > dA.z) atomicMax(dn + 2, __float_as_uint(v2));
        if (v3 > dA.w) atomicMax(dn + 3, __float_as_uint(v3));
        if (v4 > dB.x) atomicMax(dn + 4, __float_as_uint(v4));
        if (v5 > dB.y) atomicMax(dn + 5, __float_as_uint(v5));
        if (v6 > dB.z) atomicMax(dn + 6, __float_as_uint(v6));
        if (v7 > dB.w) atomicMax(dn + 7, __float_as_uint(v7));
    }
}

// ---------------- kernel 3: convert n32 -> c16 (2 rows/thread) ------------
__global__ void convert_kernel() {
    int i = blockIdx.x * blockDim.x + threadIdx.x;   // 8-float chunk index
    const int n8 = NN * MDIM / 8;
    if (i >= n8) return;
    const float4* pp = reinterpret_cast<const float4*>(g_n32pos) + i * 2;
    const float4* dp = reinterpret_cast<const float4*>(g_n32dom) + i * 2;
    float4 pA = pp[0], pB = pp[1];
    float4 dA = dp[0], dB = dp[1];
    __half2 h;
    uint4 po, dd;
    h = __floats2half2_rn(pA.x, pA.y); po.x = *reinterpret_cast<unsigned*>(&h);
    h = __floats2half2_rn(pA.z, pA.w); po.y = *reinterpret_cast<unsigned*>(&h);
    h = __floats2half2_rn(pB.x, pB.y); po.z = *reinterpret_cast<unsigned*>(&h);
    h = __floats2half2_rn(pB.z, pB.w); po.w = *reinterpret_cast<unsigned*>(&h);
    h = __floats2half2_rn(dA.x, dA.y); dd.x = *reinterpret_cast<unsigned*>(&h);
    h = __floats2half2_rn(dA.z, dA.w); dd.y = *reinterpret_cast<unsigned*>(&h);
    h = __floats2half2_rn(dB.x, dB.y); dd.z = *reinterpret_cast<unsigned*>(&h);
    h = __floats2half2_rn(dB.z, dB.w); dd.w = *reinterpret_cast<unsigned*>(&h);
    reinterpret_cast<uint4*>(g_c16pos)[i] = po;
    reinterpret_cast<uint4*>(g_c16dom)[i] = dd;
}

// ---------------- kernel 4: propagation rounds 2-3 (mirror filter) ---------
// 2 lanes per edge, paired spatial+dom edges, mirror-based filter (32 regs).
__global__ void prop_kernel(const int* __restrict__ si, const int* __restrict__ di) {
    long long t = (long long)blockIdx.x * blockDim.x + threadIdx.x;
    if (t >= (long long)ES * 2) return;
    int p = (int)(t >> 1);       // edge id in each set
    int sub = (int)(t & 1);      // half-row (8 channels)

    int s0 = si[p], d0 = si[ES + p];
    int s1 = di[p], d1 = di[ED + p];
    float ew0 = g_ew_s[p];
    float ew1 = g_ew_d[p];

    uint4 sr0 = *reinterpret_cast<const uint4*>(&g_c16pos[(size_t)s0 * MDIM + sub * 8]);
    uint4 dr0 = *reinterpret_cast<const uint4*>(&g_c16pos[(size_t)d0 * MDIM + sub * 8]);
    uint4 sr1 = *reinterpret_cast<const uint4*>(&g_c16dom[(size_t)s1 * MDIM + sub * 8]);
    uint4 dr1 = *reinterpret_cast<const uint4*>(&g_c16dom[(size_t)d1 * MDIM + sub * 8]);

    {
        const __half2* sh = reinterpret_cast<const __half2*>(&sr0);
        const __half2* dh = reinterpret_cast<const __half2*>(&dr0);
        unsigned int* dn = reinterpret_cast<unsigned int*>(&g_n32pos[(size_t)d0 * MDIM + sub * 8]);
#pragma unroll
        for (int j = 0; j < 4; j++) {
            float2 s = __half22float2(sh[j]);
            float2 d = __half22float2(dh[j]);
            float v0 = s.x * ew0, v1 = s.y * ew0;
            if (v0 > d.x) atomicMax(dn + 2 * j + 0, __float_as_uint(v0));
            if (v1 > d.y) atomicMax(dn + 2 * j + 1, __float_as_uint(v1));
        }
    }
    {
        const __half2* sh = reinterpret_cast<const __half2*>(&sr1);
        const __half2* dh = reinterpret_cast<const __half2*>(&dr1);
        unsigned int* dn = reinterpret_cast<unsigned int*>(&g_n32dom[(size_t)d1 * MDIM + sub * 8]);
#pragma unroll
        for (int j = 0; j < 4; j++) {
            float2 s = __half22float2(sh[j]);
            float2 d = __half22float2(dh[j]);
            float v0 = s.x * ew1, v1 = s.y * ew1;
            if (v0 > d.x) atomicMax(dn + 2 * j + 0, __float_as_uint(v0));
            if (v1 > d.y) atomicMax(dn + 2 * j + 1, __float_as_uint(v1));
        }
    }
}

// ---------------- kernel 5: final max --------------------------------------
__global__ void final_kernel(const float* __restrict__ mask, float* __restrict__ out) {
    int i = blockIdx.x * blockDim.x + threadIdx.x;
    const int n4 = NN * MDIM / 4;
    if (i >= n4) return;
    float4 m = reinterpret_cast<const float4*>(mask)[i];
    float4 p = reinterpret_cast<const float4*>(g_n32pos)[i];
    float4 d = reinterpret_cast<const float4*>(g_n32dom)[i];
    float4 r;
    r.x = fmaxf(m.x, fmaxf(p.x, d.x));
    r.y = fmaxf(m.y, fmaxf(p.y, d.y));
    r.z = fmaxf(m.z, fmaxf(p.z, d.z));
    r.w = fmaxf(m.w, fmaxf(p.w, d.w));
    reinterpret_cast<float4*>(out)[i] = r;
}

// ---------------- launch -------------------------------------------------
extern "C" void kernel_launch(void* const* d_in, const int* in_sizes, int n_in,
                              void* d_out, int out_size) {
    const float* x     = (const float*)d_in[0];
    const float* mask  = (const float*)d_in[1];
    const int*   si    = (const int*)d_in[2];
    const int*   di    = (const int*)d_in[3];
    const float* sattr = (const float*)d_in[4];
    const float* dattr = (const float*)d_in[5];
    const float* Wt    = (const float*)d_in[6];
    const float* bt    = (const float*)d_in[7];
    const float* Wpos  = (const float*)d_in[8];
    const float* bpos  = (const float*)d_in[9];
    const float* Wdom  = (const float*)d_in[10];
    const float* bdom  = (const float*)d_in[11];
    float* out = (float*)d_out;

    const int n4 = NN * MDIM / 4;
    const int n8 = NN * MDIM / 8;
    const int cgrid = (n4 + 255) / 256;

    // 1. HMMA node projections + fused mask-buffer init
    proj_kernel<<<(NN + 63) / 64, 128>>>(x, Wt, bt, mask);

    // 2. fused gate + propagation round 1 (2 lanes/edge, live filter)
    {
        long long threads = (long long)(ES + ED) * 2;
        int blk = 256;
        long long grid = (threads + blk - 1) / blk;
        ewprop_kernel<<<(unsigned)grid, blk>>>(si, di, sattr, dattr, Wpos, bpos, Wdom, bdom);
    }

    // 3. rounds 2-3: convert / prop / convert / prop
    {
        long long threads = (long long)ES * 2;   // 2 edges (one per set) per thread
        int blk = 256;
        long long grid = (threads + blk - 1) / blk;

        convert_kernel<<<(n8 + 255) / 256, 256>>>();
        prop_kernel<<<(unsigned)grid, blk>>>(si, di);
        convert_kernel<<<(n8 + 255) / 256, 256>>>();
        prop_kernel<<<(unsigned)grid, blk>>>(si, di);
    }

    // 4. final: max(mask, pos, dom)
    final_kernel<<<cgrid, 256>>>(mask, out);
}